// round 13
// baseline (speedup 1.0000x reference)
#include <cuda_runtime.h>
#include <cstdint>

#define NN   50000
#define EE   800000
#define FIN  64
#define HH   128
#define GG   16
#define NB   ((NN + 255) / 256)      // 196 scan blocks

// ---------------- device scratch (static allocation only) ----------------
// Invariants maintained across graph replays (zero-init at module load):
//   g_cnt  == 0 on entry (reset by xs_kernel after fill used it as cursor)
//   g_pool == 0 on entry (zeroed by mlp_kernel after it reads the pool)
__device__ int   g_cnt  [NN];
__device__ int   g_rowptr[NN + 1];
__device__ int   g_bsum [NB];
__device__ int   g_esrc [EE];                              // src only, sorted by dst
__device__ float g_dinv [NN];
__device__ __align__(16) float g_xs [(size_t)NN * FIN];    // x * dinv (pre-scaled)
__device__ __align__(16) float g_a  [(size_t)NN * HH];     // aggregated features
__device__ __align__(16) float g_hs [(size_t)NN * HH];     // relu(h) * dinv
__device__ float g_pool [GG * HH];

// ---------------- helpers ----------------
__device__ __forceinline__ void red_add_v4(float* addr, float4 v) {
    asm volatile("red.global.add.v4.f32 [%0], {%1,%2,%3,%4};"
                 :: "l"(addr), "f"(v.x), "f"(v.y), "f"(v.z), "f"(v.w)
                 : "memory");
}

// packed fp32x2 ops (sm_100+ baseline PTX; SASS FFMA2/FADD2 — 2x fp32 rate)
__device__ __forceinline__ void fma2(unsigned long long& d,
                                     unsigned long long a, unsigned long long b) {
    asm("fma.rn.f32x2 %0, %1, %2, %3;" : "=l"(d) : "l"(a), "l"(b), "l"(d));
}
__device__ __forceinline__ void fadd2(unsigned long long& d, unsigned long long a) {
    asm("add.rn.f32x2 %0, %1, %2;" : "=l"(d) : "l"(d), "l"(a));
}
__device__ __forceinline__ unsigned long long dup2(float x) {
    unsigned long long r;
    asm("mov.b64 %0, {%1, %1};" : "=l"(r) : "f"(x));
    return r;
}
__device__ __forceinline__ float2 unpk2(unsigned long long v) {
    float2 r;
    asm("mov.b64 {%0, %1}, %2;" : "=f"(r.x), "=f"(r.y) : "l"(v));
    return r;
}

// ---------------- CSR build ----------------
__global__ void deg_kernel(const int* __restrict__ dst) {
    int e = blockIdx.x * blockDim.x + threadIdx.x;
    if (e < EE) atomicAdd(&g_cnt[dst[e]], 1);    // g_cnt starts at 0 (invariant)
}

__global__ __launch_bounds__(256) void scan_partial_kernel() {
    __shared__ int sm[256];
    int i = blockIdx.x * 256 + threadIdx.x;
    int t = threadIdx.x;
    sm[t] = (i < NN) ? g_cnt[i] : 0;
    __syncthreads();
#pragma unroll
    for (int s = 128; s > 0; s >>= 1) {
        if (t < s) sm[t] += sm[t + s];
        __syncthreads();
    }
    if (t == 0) g_bsum[blockIdx.x] = sm[0];
}

// bsum scan redone per block (cheap) + per-element exclusive scan
__global__ __launch_bounds__(256) void scan_apply_kernel() {
    __shared__ int sb[256];
    __shared__ int sm[256];
    int t = threadIdx.x;

    int bv = (t < NB) ? g_bsum[t] : 0;
    sb[t] = bv;
    __syncthreads();
#pragma unroll
    for (int s = 1; s < 256; s <<= 1) {
        int x = (t >= s) ? sb[t - s] : 0;
        __syncthreads();
        sb[t] += x;
        __syncthreads();
    }
    int block_off = (blockIdx.x == 0) ? 0 : sb[blockIdx.x - 1];

    int i = blockIdx.x * 256 + t;
    int deg = (i < NN) ? g_cnt[i] : 0;
    sm[t] = deg;
    __syncthreads();
#pragma unroll
    for (int s = 1; s < 256; s <<= 1) {
        int x = (t >= s) ? sm[t - s] : 0;
        __syncthreads();
        sm[t] += x;
        __syncthreads();
    }
    if (i < NN) {
        int off = block_off + sm[t] - deg;            // exclusive prefix
        g_rowptr[i] = off;
        g_cnt[i]    = off;                             // cursor for fill
        g_dinv[i]   = rsqrtf((float)(deg + 1));        // +1 self loop
    }
    if (blockIdx.x == 0 && t == 0) g_rowptr[NN] = EE;
}

__global__ void fill_kernel(const int* __restrict__ src, const int* __restrict__ dst) {
    int e = blockIdx.x * blockDim.x + threadIdx.x;
    if (e >= EE) return;
    int s = src[e];
    int p = atomicAdd(&g_cnt[dst[e]], 1);
    g_esrc[p] = s;                                     // norm no longer stored
}

// ---------------- xs = x * dinv; also restores g_cnt invariant ----------------
__global__ __launch_bounds__(256) void xs_kernel(const float* __restrict__ x) {
    int gid = blockIdx.x * blockDim.x + threadIdx.x;   // NN*16 float4 chunks
    if (gid >= NN * (FIN / 4)) return;
    int row = gid >> 4;
    if ((gid & 15) == 0) g_cnt[row] = 0;               // reset cursor residue
    float dn = __ldg(&g_dinv[row]);
    float4 v = reinterpret_cast<const float4*>(x)[gid];
    v.x *= dn; v.y *= dn; v.z *= dn; v.w *= dn;
    reinterpret_cast<float4*>(g_xs)[gid] = v;
}

// ---------------- layer-1 aggregation over xs (64 features) ----------------
// warp per node, float2 per lane; a_i = dinv_i * (xs_i + sum xs_src)
__global__ __launch_bounds__(256) void msg_x_kernel() {
    int gid  = blockIdx.x * blockDim.x + threadIdx.x;
    int i    = gid >> 5;
    int lane = gid & 31;
    if (i >= NN) return;

    int beg = __ldg(&g_rowptr[i]);
    int end = __ldg(&g_rowptr[i + 1]);

    unsigned long long acc = 0ull;
    const unsigned long long* xsp = reinterpret_cast<const unsigned long long*>(g_xs);
    int e  = beg;
    int n4 = beg + ((end - beg) & ~3);
    for (; e < n4; e += 4) {
        int s0 = __ldg(&g_esrc[e]);
        int s1 = __ldg(&g_esrc[e + 1]);
        int s2 = __ldg(&g_esrc[e + 2]);
        int s3 = __ldg(&g_esrc[e + 3]);
        unsigned long long v0 = __ldg(&xsp[(size_t)s0 * (FIN / 2) + lane]);
        unsigned long long v1 = __ldg(&xsp[(size_t)s1 * (FIN / 2) + lane]);
        unsigned long long v2 = __ldg(&xsp[(size_t)s2 * (FIN / 2) + lane]);
        unsigned long long v3 = __ldg(&xsp[(size_t)s3 * (FIN / 2) + lane]);
        fadd2(acc, v0); fadd2(acc, v1); fadd2(acc, v2); fadd2(acc, v3);
    }
    for (; e < end; e++) {
        int s0 = __ldg(&g_esrc[e]);
        fadd2(acc, __ldg(&xsp[(size_t)s0 * (FIN / 2) + lane]));
    }
    fadd2(acc, xsp[(size_t)i * (FIN / 2) + lane]);     // self term

    float dn = __ldg(&g_dinv[i]);
    float2 r = unpk2(acc);
    r.x *= dn; r.y *= dn;
    *reinterpret_cast<float2*>(g_a + (size_t)i * FIN + lane * 2) = r;
}

// ---------------- aggregation over hs (128 features), optional pool sink ------
__global__ __launch_bounds__(256) void msg_h_kernel(int do_pool,
                                                    const int* __restrict__ batch) {
    int gid  = blockIdx.x * blockDim.x + threadIdx.x;
    int i    = gid >> 5;
    int lane = gid & 31;
    if (i >= NN) return;

    int beg = __ldg(&g_rowptr[i]);
    int end = __ldg(&g_rowptr[i + 1]);

    unsigned long long a0 = 0ull, a1 = 0ull;
    const ulonglong2* hsp = reinterpret_cast<const ulonglong2*>(g_hs);
    int e  = beg;
    int n4 = beg + ((end - beg) & ~3);
    for (; e < n4; e += 4) {
        int s0 = __ldg(&g_esrc[e]);
        int s1 = __ldg(&g_esrc[e + 1]);
        int s2 = __ldg(&g_esrc[e + 2]);
        int s3 = __ldg(&g_esrc[e + 3]);
        ulonglong2 v0 = __ldg(&hsp[(size_t)s0 * 32 + lane]);
        ulonglong2 v1 = __ldg(&hsp[(size_t)s1 * 32 + lane]);
        ulonglong2 v2 = __ldg(&hsp[(size_t)s2 * 32 + lane]);
        ulonglong2 v3 = __ldg(&hsp[(size_t)s3 * 32 + lane]);
        fadd2(a0, v0.x); fadd2(a1, v0.y);
        fadd2(a0, v1.x); fadd2(a1, v1.y);
        fadd2(a0, v2.x); fadd2(a1, v2.y);
        fadd2(a0, v3.x); fadd2(a1, v3.y);
    }
    for (; e < end; e++) {
        int s0 = __ldg(&g_esrc[e]);
        ulonglong2 v0 = __ldg(&hsp[(size_t)s0 * 32 + lane]);
        fadd2(a0, v0.x); fadd2(a1, v0.y);
    }
    {   // self term
        ulonglong2 vs = hsp[(size_t)i * 32 + lane];
        fadd2(a0, vs.x); fadd2(a1, vs.y);
    }

    float dn = __ldg(&g_dinv[i]);
    float2 r0 = unpk2(a0);
    float2 r1 = unpk2(a1);
    float4 r = make_float4(r0.x * dn, r0.y * dn, r1.x * dn, r1.y * dn);

    if (do_pool) {
        int g = __ldg(&batch[i]);
        red_add_v4(&g_pool[g * 128 + lane * 4], r);    // layer-4: straight to pool
    } else {
        *reinterpret_cast<float4*>(&g_a[(size_t)i * 128 + lane * 4]) = r;
    }
}

// ---------------- SGEMM (FFMA2): hs = relu(a @ W + b) * dinv[row] ----------------
// BM=128, BN=128, BK=16, thread tile 8x8 as 8x(4 float2), 256 threads
__global__ __launch_bounds__(256) void gemm_kernel(
    const float* __restrict__ A, const float* __restrict__ B,
    const float* __restrict__ bias, float* __restrict__ C, int M, int K)
{
    __shared__ float As[16][128];
    __shared__ float Bs[16][128];

    const int tid = threadIdx.x;
    const int tr  = tid >> 4;          // 0..15
    const int tc  = tid & 15;          // 0..15
    const int block_row = blockIdx.x * 128;

    unsigned long long acc[8][4];
#pragma unroll
    for (int m = 0; m < 8; m++)
#pragma unroll
        for (int n = 0; n < 4; n++) acc[m][n] = 0ull;

    for (int k0 = 0; k0 < K; k0 += 16) {
#pragma unroll
        for (int i = 0; i < 2; i++) {
            int f   = tid + i * 256;
            int row = f >> 2;
            int c4  = (f & 3) * 4;
            int grow = block_row + row;
            float4 v = make_float4(0.f, 0.f, 0.f, 0.f);
            if (grow < M)
                v = *reinterpret_cast<const float4*>(A + (size_t)grow * K + k0 + c4);
            As[c4 + 0][row] = v.x;
            As[c4 + 1][row] = v.y;
            As[c4 + 2][row] = v.z;
            As[c4 + 3][row] = v.w;
        }
#pragma unroll
        for (int i = 0; i < 2; i++) {
            int f   = tid + i * 256;
            int row = f >> 5;
            int c4  = (f & 31) * 4;
            float4 v = *reinterpret_cast<const float4*>(B + (size_t)(k0 + row) * 128 + c4);
            *reinterpret_cast<float4*>(&Bs[row][c4]) = v;
        }
        __syncthreads();

#pragma unroll
        for (int k = 0; k < 16; k++) {
            float4 a03 = *reinterpret_cast<const float4*>(&As[k][tr * 8]);
            float4 a47 = *reinterpret_cast<const float4*>(&As[k][tr * 8 + 4]);
            ulonglong2 b01 = *reinterpret_cast<const ulonglong2*>(&Bs[k][tc * 8]);
            ulonglong2 b23 = *reinterpret_cast<const ulonglong2*>(&Bs[k][tc * 8 + 4]);
            unsigned long long bb[4] = { b01.x, b01.y, b23.x, b23.y };
            float av[8] = { a03.x, a03.y, a03.z, a03.w, a47.x, a47.y, a47.z, a47.w };
#pragma unroll
            for (int m = 0; m < 8; m++) {
                unsigned long long a2 = dup2(av[m]);
#pragma unroll
                for (int n = 0; n < 4; n++) fma2(acc[m][n], a2, bb[n]);
            }
        }
        __syncthreads();
    }

    // epilogue: + bias, relu, * dinv[row]  -> pre-scaled activation hs
    float4 bv0 = *reinterpret_cast<const float4*>(bias + tc * 8);
    float4 bv1 = *reinterpret_cast<const float4*>(bias + tc * 8 + 4);
#pragma unroll
    for (int m = 0; m < 8; m++) {
        int grow = block_row + tr * 8 + m;
        if (grow < M) {
            float dn = __ldg(&g_dinv[grow]);
            float2 r0 = unpk2(acc[m][0]);
            float2 r1 = unpk2(acc[m][1]);
            float2 r2 = unpk2(acc[m][2]);
            float2 r3 = unpk2(acc[m][3]);
            float4 o0 = make_float4(fmaxf(r0.x + bv0.x, 0.f) * dn,
                                    fmaxf(r0.y + bv0.y, 0.f) * dn,
                                    fmaxf(r1.x + bv0.z, 0.f) * dn,
                                    fmaxf(r1.y + bv0.w, 0.f) * dn);
            float4 o1 = make_float4(fmaxf(r2.x + bv1.x, 0.f) * dn,
                                    fmaxf(r2.y + bv1.y, 0.f) * dn,
                                    fmaxf(r3.x + bv1.z, 0.f) * dn,
                                    fmaxf(r3.y + bv1.w, 0.f) * dn);
            float4* cp = reinterpret_cast<float4*>(C + (size_t)grow * 128 + tc * 8);
            cp[0] = o0;
            cp[1] = o1;
        }
    }
}

// ---------------- head: W4 + bias + MLP; zeroes g_pool after use ----------------
__device__ __forceinline__ int lower_bound_batch(const int* b, int key) {
    int lo = 0, hi = NN;
    while (lo < hi) {
        int mid = (lo + hi) >> 1;
        if (b[mid] < key) lo = mid + 1; else hi = mid;
    }
    return lo;
}

__global__ __launch_bounds__(256) void mlp_kernel(
    const float* __restrict__ W4, const float* __restrict__ b4,
    const float* __restrict__ lw1, const float* __restrict__ lb1,
    const float* __restrict__ lw2, const float* __restrict__ lb2,
    const int* __restrict__ batch, float* __restrict__ out)
{
    __shared__ float pa [GG][HH];
    __shared__ float h4 [GG][HH];
    __shared__ float mid[GG][64];
    __shared__ float cnt[GG];
    int t = threadIdx.x;

    if (t < GG) {
        int lo = lower_bound_batch(batch, t);
        int hi = lower_bound_batch(batch, t + 1);
        cnt[t] = fmaxf((float)(hi - lo), 1.0f);
    }
    for (int i = t; i < GG * HH; i += 256) {
        pa[i / HH][i % HH] = g_pool[i];
        g_pool[i] = 0.f;                       // restore invariant for next replay
    }
    __syncthreads();
    for (int i = t; i < GG * HH; i += 256)
        pa[i / HH][i % HH] /= cnt[i / HH];
    __syncthreads();

    // h4 = pa @ W4 + b4    (16 x 128, K=128) — 8 outputs per thread
    {
        int g  = t >> 4;
        int nb = (t & 15) * 8;
        float s[8];
#pragma unroll
        for (int j = 0; j < 8; j++) s[j] = b4[nb + j];
        for (int k = 0; k < 128; k++) {
            float a = pa[g][k];
            const float* wr = W4 + (size_t)k * 128 + nb;
#pragma unroll
            for (int j = 0; j < 8; j++) s[j] = fmaf(a, wr[j], s[j]);
        }
#pragma unroll
        for (int j = 0; j < 8; j++) h4[g][nb + j] = s[j];
    }
    __syncthreads();

    // mid = relu(h4 @ lw1 + lb1)    (16 x 64, K=128) — 4 outputs per thread
    {
        int g  = t >> 4;
        int jb = (t & 15) * 4;
        float s[4];
#pragma unroll
        for (int j = 0; j < 4; j++) s[j] = lb1[jb + j];
        for (int k = 0; k < 128; k++) {
            float a = h4[g][k];
            const float* wr = lw1 + (size_t)k * 64 + jb;
#pragma unroll
            for (int j = 0; j < 4; j++) s[j] = fmaf(a, wr[j], s[j]);
        }
#pragma unroll
        for (int j = 0; j < 4; j++) mid[g][jb + j] = fmaxf(s[j], 0.f);
    }
    __syncthreads();

    if (t < GG * 2) {
        int g = t >> 1, c = t & 1;
        float s = lb2[c];
#pragma unroll 8
        for (int k = 0; k < 64; k++) s = fmaf(mid[g][k], lw2[k * 2 + c], s);
        out[g * 2 + c] = s;
    }
}

// ---------------- host launcher ----------------
extern "C" void kernel_launch(void* const* d_in, const int* in_sizes, int n_in,
                              void* d_out, int out_size)
{
    const float* x    = (const float*)d_in[0];
    const int*   ei   = (const int*)  d_in[1];
    const int*   batch= (const int*)  d_in[2];
    const float* W1 = (const float*)d_in[3];  const float* b1 = (const float*)d_in[4];
    const float* W2 = (const float*)d_in[5];  const float* b2 = (const float*)d_in[6];
    const float* W3 = (const float*)d_in[7];  const float* b3 = (const float*)d_in[8];
    const float* W4 = (const float*)d_in[9];  const float* b4 = (const float*)d_in[10];
    const float* lw1= (const float*)d_in[11]; const float* lb1= (const float*)d_in[12];
    const float* lw2= (const float*)d_in[13]; const float* lb2= (const float*)d_in[14];
    float* out = (float*)d_out;

    const int* src = ei;        // edge_index[0]  (message source)
    const int* dst = ei + EE;   // edge_index[1]  (aggregation target)

    float *p_a, *p_hs;
    cudaGetSymbolAddress((void**)&p_a,  g_a);
    cudaGetSymbolAddress((void**)&p_hs, g_hs);

    const int gemm_blocks = (NN + 127) / 128;
    const int msg_blocks  = (NN * 32 + 255) / 256;

    // ---- CSR build (g_cnt invariant: zero on entry) ----
    deg_kernel         <<<(EE + 255) / 256, 256>>>(dst);       // 1
    scan_partial_kernel<<<NB, 256>>>();                        // 2
    scan_apply_kernel  <<<NB, 256>>>();                        // 3
    fill_kernel        <<<(EE + 255) / 256, 256>>>(src, dst);  // 4 (profiled slot)
    xs_kernel          <<<(NN * 16 + 255) / 256, 256>>>(x);    // 5

    // ---- layer 1: agg(xs) -> gemm(relu, *dinv) ----
    msg_x_kernel<<<msg_blocks, 256>>>();                                    // 6
    gemm_kernel <<<gemm_blocks, 256>>>(p_a, W1, b1, p_hs, NN, FIN);         // 7
    // ---- layers 2,3 ----
    msg_h_kernel<<<msg_blocks, 256>>>(0, batch);                            // 8
    gemm_kernel <<<gemm_blocks, 256>>>(p_a, W2, b2, p_hs, NN, HH);          // 9
    msg_h_kernel<<<msg_blocks, 256>>>(0, batch);                            // 10
    gemm_kernel <<<gemm_blocks, 256>>>(p_a, W3, b3, p_hs, NN, HH);          // 11
    // ---- layer 4: agg(hs3) pooled directly; W4+b4 folded into head ----
    msg_h_kernel<<<msg_blocks, 256>>>(1, batch);                            // 12
    mlp_kernel  <<<1, 256>>>(W4, b4, lw1, lb1, lw2, lb2, batch, out);       // 13
}